// round 10
// baseline (speedup 1.0000x reference)
#include <cuda_runtime.h>
#include <cuda_bf16.h>
#include <cstdint>

// ---------------------------------------------------------------------------
// MultiDimensionalRNN: skewed 2D RNN (diagonal recurrence) + FC head.
//
//   act[r,c] = tanh(k0*act[r-1,c-1] + k1*act[r,c-1] + bs + in[r,c])   (skewed)
//
// R10: fully-overlapped cross-stage handoff. R9 paid ~1000 cyc of exposed
// flag-poll + boundary-load latency per 16-column chunk (the real binder at
// ~260 cyc/col). Now each stage keeps a shadow copy of the producer's flag,
// prefetches the NEXT chunk's boundary values before computing the current
// chunk whenever the shadow already covers them, and overlaps a fresh
// acquire-poll with the chunk compute. Spin only happens when the producer is
// genuinely behind (self-stabilizing: lag grows until prefetch always hits).
//
// Layouts (from R9): prep kernel materializes pre-affined input in a skewed,
// padded [2048 x 4096] layout; scan does float4 chunk I/O; activations land
// skewed in g_A; FC reads them contiguously.
//
// 32 single-warp pipeline stages, 64 rows each, 2 adjacent rows per lane.
// State in r-form: r = 1/(1 + 2^(LAM2*x)), tanh(x) = 1 - 2r  (~1e-6/step).
// ---------------------------------------------------------------------------

#define HH 2048
#define WW 2048
#define WS 4096                     // padded skewed stride (floats)
#define NSTAGE 32
#define ROWS_PER_STAGE 64           // 32 lanes * 2 rows
#define CH 16                       // columns per sync chunk (4 float4 / row)
#define NCOL 4096                   // 4095 needed; col 4095 harmless
#define NCHUNK (NCOL / CH)          // 256
#define FC_IN 1024
#define FC_OUT 10
#define M_ROWS ((HH * WW) / FC_IN)  // 4096

__device__ float g_In[(size_t)HH * WS];     // pre-affined skewed input (32 MB)
__device__ float g_A [(size_t)HH * WS];     // skewed activations h (32 MB)
__device__ float g_Bnd[NSTAGE * NCOL];      // boundary-row r-values per column
__device__ int   g_flag[NSTAGE];            // chunks completed per stage

// ---------------- PTX helpers ----------------
__device__ __forceinline__ float ex2f(float x) {
    float r; asm("ex2.approx.ftz.f32 %0, %1;" : "=f"(r) : "f"(x)); return r;
}
__device__ __forceinline__ float rcpf(float x) {
    float r; asm("rcp.approx.ftz.f32 %0, %1;" : "=f"(r) : "f"(x)); return r;
}
__device__ __forceinline__ int ld_acq(const int* p) {
    int v;
    asm volatile("ld.acquire.gpu.global.s32 %0, [%1];" : "=r"(v) : "l"(p) : "memory");
    return v;
}
__device__ __forceinline__ void st_rel(int* p, int v) {
    asm volatile("st.release.gpu.global.s32 [%0], %1;" :: "l"(p), "r"(v) : "memory");
}
__device__ __forceinline__ float ld_l2(const float* p) {
    float v;
    asm volatile("ld.relaxed.gpu.global.f32 %0, [%1];" : "=f"(v) : "l"(p) : "memory");
    return v;
}

// ---------------- prep: skew + affine + flag reset ----------------
// g_In[r][c] = Wl*img[r][c-r] + Cc  if 0 <= c-r < W,  else Cc
__global__ void __launch_bounds__(256)
prep_kernel(const float* __restrict__ img,
            const float* __restrict__ w_in,    const float* __restrict__ b_in,
            const float* __restrict__ w_state, const float* __restrict__ b_state)
{
    const float LAM2 = 2.8853900817779268f;     // 2*log2(e)
    const float Wl = LAM2 * w_in[0];
    const float Cc = LAM2 * (w_state[0] + w_state[1] + b_state[0] + b_in[0]);

    int t = blockIdx.x * blockDim.x + threadIdx.x;   // [0, 2048*1024)
    int r  = t >> 10;                                // row
    int c0 = (t & 1023) << 2;                        // col base (float4)
    float v[4];
    #pragma unroll
    for (int u = 0; u < 4; u++) {
        int d = c0 + u - r;                          // unskewed column
        v[u] = (d >= 0 && d < WW)
             ? fmaf(Wl, __ldg(img + (size_t)r * WW + d), Cc)
             : Cc;
    }
    *(float4*)(g_In + (size_t)r * WS + c0) = make_float4(v[0], v[1], v[2], v[3]);

    if (t < NSTAGE) g_flag[t] = 0;                   // fold flag reset in here
}

// ---------------- wavefront scan ----------------
__global__ void __launch_bounds__(32, 1)
scan_kernel(const float* __restrict__ w_state)
{
    const int s    = blockIdx.x;
    const int lane = threadIdx.x;

    const float LAM2 = 2.8853900817779268f;
    const float A = -2.0f * LAM2 * w_state[0];       // coeff on r_up
    const float B = -2.0f * LAM2 * w_state[1];       // coeff on r_self

    const int R0 = s * ROWS_PER_STAGE + lane * 2;
    const int R1 = R0 + 1;
    const float4* p0 = (const float4*)(g_In + (size_t)R0 * WS);
    const float4* p1 = (const float4*)(g_In + (size_t)R1 * WS);
    float4* o0p = (float4*)(g_A + (size_t)R0 * WS);
    float4* o1p = (float4*)(g_A + (size_t)R1 * WS);

    float*       bout = g_Bnd + s * NCOL;
    const float* bin  = g_Bnd + (s - 1) * NCOL;      // never deref'd for s==0
    const int*   pflag = &g_flag[(s > 0) ? (s - 1) : 0];
    const bool   last  = (s == NSTAGE - 1);

    float r0 = 0.5f, r1 = 0.5f;                      // r-form of h = 0

    // prefetch chunk 0 inputs
    float4 in0[4], in1[4];
    #pragma unroll
    for (int t = 0; t < 4; t++) { in0[t] = p0[t]; in1[t] = p1[t]; }

    // prologue: boundary values for chunk 0 (+ initial flag shadow)
    float bnd[CH];
    int flagval = 0;
    if (s > 0) {
        do { flagval = ld_acq(pflag); } while (flagval < 1);
        #pragma unroll
        for (int j = 0; j < CH; j++)
            bnd[j] = (j >= 1) ? ld_l2(bin + j - 1) : 0.5f;
    } else {
        #pragma unroll
        for (int j = 0; j < CH; j++) bnd[j] = 0.5f;  // row -1 is h=0 forever
    }

    for (int k = 0; k < NCHUNK; k++) {
        const int c0 = k * CH;
        const int q0 = c0 >> 2;                      // float4 index of chunk base
        const bool haveNext = (k + 1 < NCHUNK);

        // --- software-pipeline: next-chunk input loads ---
        float4 nx0[4], nx1[4];
        if (haveNext) {
            #pragma unroll
            for (int t = 0; t < 4; t++) { nx0[t] = p0[q0 + 4 + t]; nx1[t] = p1[q0 + 4 + t]; }
        }

        // --- speculative boundary prefetch for chunk k+1 (overlaps compute) ---
        float bndN[CH];
        bool  pf   = false;
        int   poll = flagval;
        if (s > 0 && haveNext) {
            if (flagval >= k + 2) {                  // acquire-observed earlier: safe
                #pragma unroll
                for (int j = 0; j < CH; j++)
                    bndN[j] = ld_l2(bin + c0 + CH - 1 + j);
                pf = true;
            }
            poll = ld_acq(pflag);                    // in-flight; consumed post-compute
        }

        // --- unpack input float4s ---
        float g0[CH], g1[CH];
        #pragma unroll
        for (int t = 0; t < 4; t++) {
            g0[4*t+0] = in0[t].x; g0[4*t+1] = in0[t].y; g0[4*t+2] = in0[t].z; g0[4*t+3] = in0[t].w;
            g1[4*t+0] = in1[t].x; g1[4*t+1] = in1[t].y; g1[4*t+2] = in1[t].z; g1[4*t+3] = in1[t].w;
        }

        // --- the recurrence (all in registers) ---
        float o0[CH], o1[CH];
        #pragma unroll
        for (int j = 0; j < CH; j++) {
            float up   = __shfl_up_sync(0xffffffffu, r1, 1); // lane-1 row R0-1, prev col
            float r0up = (lane == 0) ? bnd[j] : up;
            float a0 = fmaf(A, r0up, fmaf(B, r0, g0[j]));
            float a1 = fmaf(A, r0,   fmaf(B, r1, g1[j]));    // R1's up = old r0
            float n0 = rcpf(1.0f + ex2f(a0));
            float n1 = rcpf(1.0f + ex2f(a1));
            o0[j] = fmaf(-2.0f, n0, 1.0f);
            o1[j] = fmaf(-2.0f, n1, 1.0f);
            if (!last && lane == 31) bout[c0 + j] = n1;      // boundary (r-form)
            r0 = n0; r1 = n1;
        }

        // --- aligned float4 stores of the whole chunk ---
        #pragma unroll
        for (int t = 0; t < 4; t++) {
            o0p[q0 + t] = make_float4(o0[4*t], o0[4*t+1], o0[4*t+2], o0[4*t+3]);
            o1p[q0 + t] = make_float4(o1[4*t], o1[4*t+1], o1[4*t+2], o1[4*t+3]);
        }

        if (!last && lane == 31) st_rel(&g_flag[s], k + 1);

        // --- consume in-flight poll; fall back to spin only if behind ---
        if (s > 0 && haveNext) {
            flagval = poll;
            if (!pf) {
                while (flagval < k + 2) flagval = ld_acq(pflag);
                #pragma unroll
                for (int j = 0; j < CH; j++)
                    bndN[j] = ld_l2(bin + c0 + CH - 1 + j);
            }
            #pragma unroll
            for (int j = 0; j < CH; j++) bnd[j] = bndN[j];
        }

        if (haveNext) {
            #pragma unroll
            for (int t = 0; t < 4; t++) { in0[t] = nx0[t]; in1[t] = nx1[t]; }
        }
    }
}

// ---------------- FC head: warp-per-row GEMV over skewed g_A ----------------
__global__ void __launch_bounds__(256)
fc_kernel(const float* __restrict__ fc_w, const float* __restrict__ fc_b,
          float* __restrict__ out)
{
    __shared__ float sw[FC_OUT][FC_IN];   // 40 KB
    const int tid = threadIdx.x;
    for (int i = tid; i < FC_OUT * FC_IN; i += blockDim.x)
        (&sw[0][0])[i] = fc_w[i];
    __syncthreads();

    const int warp = tid >> 5, lane = tid & 31;
    const int m = blockIdx.x * (blockDim.x >> 5) + warp;
    const int r = m >> 1, h = m & 1;
    // unskewed[r, c] = act[r, r+c];  FC row m covers cols h*1024 .. h*1024+1023
    const float* x = g_A + (size_t)r * WS + r + h * FC_IN;

    float acc[FC_OUT];
    #pragma unroll
    for (int o = 0; o < FC_OUT; o++) acc[o] = 0.0f;

    #pragma unroll 4
    for (int k = lane; k < FC_IN; k += 32) {
        float xv = x[k];
        #pragma unroll
        for (int o = 0; o < FC_OUT; o++)
            acc[o] = fmaf(xv, sw[o][k], acc[o]);
    }
    #pragma unroll
    for (int o = 0; o < FC_OUT; o++) {
        #pragma unroll
        for (int d = 16; d > 0; d >>= 1)
            acc[o] += __shfl_down_sync(0xffffffffu, acc[o], d);
    }
    if (lane == 0) {
        #pragma unroll
        for (int o = 0; o < FC_OUT; o++)
            out[(size_t)m * FC_OUT + o] = acc[o] + fc_b[o];
    }
}

// ---------------- launch ----------------
extern "C" void kernel_launch(void* const* d_in, const int* in_sizes, int n_in,
                              void* d_out, int out_size)
{
    (void)in_sizes; (void)n_in; (void)out_size;
    const float* x       = (const float*)d_in[0];  // [1,2048,2048]
    const float* w_in    = (const float*)d_in[1];  // [1]
    const float* b_in    = (const float*)d_in[2];  // [1]
    const float* w_state = (const float*)d_in[3];  // [2] = {k0, k1}
    const float* b_state = (const float*)d_in[4];  // [1]
    const float* fc_w    = (const float*)d_in[5];  // [10,1024]
    const float* fc_b    = (const float*)d_in[6];  // [10]
    float* out = (float*)d_out;                    // [4096,10]

    prep_kernel<<<(HH * (WS / 4)) / 256, 256>>>(x, w_in, b_in, w_state, b_state);
    scan_kernel<<<NSTAGE, 32>>>(w_state);
    fc_kernel<<<M_ROWS / 8, 256>>>(fc_w, fc_b, out);
}

// round 14
// speedup vs baseline: 1.9495x; 1.9495x over previous
#include <cuda_runtime.h>
#include <cuda_bf16.h>
#include <cstdint>

// ---------------------------------------------------------------------------
// MultiDimensionalRNN: skewed 2D RNN (diagonal recurrence) + FC head.
//
//   act[r,c] = tanh(k0*act[r-1,c-1] + k1*act[r,c-1] + bs + in[r,c])   (skewed)
//
// R11: sentinel-in-data cross-stage handoff. R9/R10 paid ~900 cyc/chunk of
// exposed flag+boundary latency (R10's flag-shadow overlap never engaged: its
// prefetch gate needed lag>=3 chunks and its fallback was as slow as R9).
// Now g_Bnd is poisoned (-2.0f, outside the r-range [0,1]) by the prep kernel
// each replay, and the boundary VALUES are their own readiness flags: the
// consumer speculatively loads next-chunk boundaries (MLP=16) before compute,
// then validates and retries only still-poison entries after compute. A
// non-poison 4B read is guaranteed to be the real value (written once per
// replay, atomic, kernel-boundary reset) -- no acquire/release needed, and
// partial misses cost one L2 round trip instead of a full serial reload.
//
// Layouts (R9): prep materializes pre-affined input skewed+padded [2048x4096];
// scan does float4 chunk I/O; activations land skewed in g_A; FC reads them
// contiguously. 32 single-warp stages, 64 rows each, 2 adjacent rows/lane.
// State in r-form: r = 1/(1 + 2^(LAM2*x)), tanh(x) = 1 - 2r  (~1e-6/step).
// ---------------------------------------------------------------------------

#define HH 2048
#define WW 2048
#define WS 4096                     // padded skewed stride (floats)
#define NSTAGE 32
#define ROWS_PER_STAGE 64           // 32 lanes * 2 rows
#define CH 16                       // columns per sync chunk (4 float4 / row)
#define NCOL 4096                   // 4095 needed; col 4095 harmless
#define NCHUNK (NCOL / CH)          // 256
#define FC_IN 1024
#define FC_OUT 10
#define M_ROWS ((HH * WW) / FC_IN)  // 4096
#define POISON_BITS 0xC0000000u     // -2.0f : outside r-range [0,1]

__device__ float g_In[(size_t)HH * WS];     // pre-affined skewed input (32 MB)
__device__ float g_A [(size_t)HH * WS];     // skewed activations h (32 MB)
__device__ float g_Bnd[NSTAGE * NCOL];      // boundary-row r-values (self-flagging)

// ---------------- PTX helpers ----------------
__device__ __forceinline__ float ex2f(float x) {
    float r; asm("ex2.approx.ftz.f32 %0, %1;" : "=f"(r) : "f"(x)); return r;
}
__device__ __forceinline__ float rcpf(float x) {
    float r; asm("rcp.approx.ftz.f32 %0, %1;" : "=f"(r) : "f"(x)); return r;
}
// L2-strong load/store: coherent across CTAs, never a stale L1 line.
__device__ __forceinline__ float ld_l2(const float* p) {
    float v;
    asm volatile("ld.relaxed.gpu.global.f32 %0, [%1];" : "=f"(v) : "l"(p) : "memory");
    return v;
}
__device__ __forceinline__ void st_l2(float* p, float v) {
    asm volatile("st.relaxed.gpu.global.f32 [%0], %1;" :: "l"(p), "f"(v) : "memory");
}

// ---------------- prep: skew + affine + boundary poison ----------------
// g_In[r][c] = Wl*img[r][c-r] + Cc  if 0 <= c-r < W,  else Cc
__global__ void __launch_bounds__(256)
prep_kernel(const float* __restrict__ img,
            const float* __restrict__ w_in,    const float* __restrict__ b_in,
            const float* __restrict__ w_state, const float* __restrict__ b_state)
{
    const float LAM2 = 2.8853900817779268f;     // 2*log2(e)
    const float Wl = LAM2 * w_in[0];
    const float Cc = LAM2 * (w_state[0] + w_state[1] + b_state[0] + b_in[0]);

    int t = blockIdx.x * blockDim.x + threadIdx.x;   // [0, 2048*1024)
    int r  = t >> 10;                                // row
    int c0 = (t & 1023) << 2;                        // col base (float4)
    float v[4];
    #pragma unroll
    for (int u = 0; u < 4; u++) {
        int d = c0 + u - r;                          // unskewed column
        v[u] = (d >= 0 && d < WW)
             ? fmaf(Wl, __ldg(img + (size_t)r * WW + d), Cc)
             : Cc;
    }
    *(float4*)(g_In + (size_t)r * WS + c0) = make_float4(v[0], v[1], v[2], v[3]);

    // re-poison the boundary ring every replay (kernel boundary orders this
    // before the scan's reads)
    if (t < NSTAGE * NCOL) g_Bnd[t] = __uint_as_float(POISON_BITS);
}

// ---------------- wavefront scan ----------------
__global__ void __launch_bounds__(32, 1)
scan_kernel(const float* __restrict__ w_state)
{
    const int s    = blockIdx.x;
    const int lane = threadIdx.x;

    const float LAM2 = 2.8853900817779268f;
    const float A = -2.0f * LAM2 * w_state[0];       // coeff on r_up
    const float B = -2.0f * LAM2 * w_state[1];       // coeff on r_self

    const int R0 = s * ROWS_PER_STAGE + lane * 2;
    const int R1 = R0 + 1;
    const float4* p0 = (const float4*)(g_In + (size_t)R0 * WS);
    const float4* p1 = (const float4*)(g_In + (size_t)R1 * WS);
    float4* o0p = (float4*)(g_A + (size_t)R0 * WS);
    float4* o1p = (float4*)(g_A + (size_t)R1 * WS);

    float*       bout = g_Bnd + s * NCOL;
    const float* bin  = g_Bnd + (s - 1) * NCOL;      // never deref'd for s==0
    const bool   last = (s == NSTAGE - 1);
    const bool   first = (s == 0);

    float r0 = 0.5f, r1 = 0.5f;                      // r-form of h = 0

    // prefetch chunk 0 inputs
    float4 in0[4], in1[4];
    #pragma unroll
    for (int t = 0; t < 4; t++) { in0[t] = p0[t]; in1[t] = p1[t]; }

    // prologue: boundary values for chunk 0 (cols -1 .. 14)
    float bnd[CH];
    bnd[0] = 0.5f;                                   // row -1 is h=0 forever
    if (!first) {
        #pragma unroll
        for (int j = 1; j < CH; j++) {
            float v;
            do { v = ld_l2(bin + j - 1); } while (__float_as_uint(v) == POISON_BITS);
            bnd[j] = v;
        }
    } else {
        #pragma unroll
        for (int j = 1; j < CH; j++) bnd[j] = 0.5f;
    }

    for (int k = 0; k < NCHUNK; k++) {
        const int c0 = k * CH;
        const int q0 = c0 >> 2;                      // float4 index of chunk base
        const bool haveNext = (k + 1 < NCHUNK);

        // --- software-pipeline: next-chunk input loads ---
        float4 nx0[4], nx1[4];
        if (haveNext) {
            #pragma unroll
            for (int t = 0; t < 4; t++) { nx0[t] = p0[q0 + 4 + t]; nx1[t] = p1[q0 + 4 + t]; }
        }

        // --- speculative boundary loads for chunk k+1 (always safe:
        //     a non-poison value is final; validated after compute) ---
        float bndN[CH];
        if (!first && haveNext) {
            #pragma unroll
            for (int j = 0; j < CH; j++)
                bndN[j] = ld_l2(bin + c0 + CH - 1 + j);
        }

        // --- unpack input float4s ---
        float g0[CH], g1[CH];
        #pragma unroll
        for (int t = 0; t < 4; t++) {
            g0[4*t+0] = in0[t].x; g0[4*t+1] = in0[t].y; g0[4*t+2] = in0[t].z; g0[4*t+3] = in0[t].w;
            g1[4*t+0] = in1[t].x; g1[4*t+1] = in1[t].y; g1[4*t+2] = in1[t].z; g1[4*t+3] = in1[t].w;
        }

        // --- the recurrence (pure registers; no memory barriers inside) ---
        float o0[CH], o1[CH], bv[CH];
        #pragma unroll
        for (int j = 0; j < CH; j++) {
            float up   = __shfl_up_sync(0xffffffffu, r1, 1); // lane-1 row R0-1, prev col
            float r0up = (lane == 0) ? bnd[j] : up;
            float a0 = fmaf(A, r0up, fmaf(B, r0, g0[j]));
            float a1 = fmaf(A, r0,   fmaf(B, r1, g1[j]));    // R1's up = old r0
            float n0 = rcpf(1.0f + ex2f(a0));
            float n1 = rcpf(1.0f + ex2f(a1));
            o0[j] = fmaf(-2.0f, n0, 1.0f);
            o1[j] = fmaf(-2.0f, n1, 1.0f);
            bv[j] = n1;
            r0 = n0; r1 = n1;
        }

        // --- publish boundary row (r-form) to the next stage, L2-strong ---
        if (!last && lane == 31) {
            #pragma unroll
            for (int j = 0; j < CH; j++) st_l2(bout + c0 + j, bv[j]);
        }

        // --- aligned float4 stores of the whole chunk ---
        #pragma unroll
        for (int t = 0; t < 4; t++) {
            o0p[q0 + t] = make_float4(o0[4*t], o0[4*t+1], o0[4*t+2], o0[4*t+3]);
            o1p[q0 + t] = make_float4(o1[4*t], o1[4*t+1], o1[4*t+2], o1[4*t+3]);
        }

        // --- validate speculative boundaries; retry only the misses ---
        if (!first && haveNext) {
            #pragma unroll
            for (int j = 0; j < CH; j++) {
                float v = bndN[j];
                while (__float_as_uint(v) == POISON_BITS)
                    v = ld_l2(bin + c0 + CH - 1 + j);
                bnd[j] = v;
            }
        }

        if (haveNext) {
            #pragma unroll
            for (int t = 0; t < 4; t++) { in0[t] = nx0[t]; in1[t] = nx1[t]; }
        }
    }
}

// ---------------- FC head: warp-per-row GEMV over skewed g_A ----------------
__global__ void __launch_bounds__(256)
fc_kernel(const float* __restrict__ fc_w, const float* __restrict__ fc_b,
          float* __restrict__ out)
{
    __shared__ float sw[FC_OUT][FC_IN];   // 40 KB
    const int tid = threadIdx.x;
    for (int i = tid; i < FC_OUT * FC_IN; i += blockDim.x)
        (&sw[0][0])[i] = fc_w[i];
    __syncthreads();

    const int warp = tid >> 5, lane = tid & 31;
    const int m = blockIdx.x * (blockDim.x >> 5) + warp;
    const int r = m >> 1, h = m & 1;
    // unskewed[r, c] = act[r, r+c];  FC row m covers cols h*1024 .. h*1024+1023
    const float* x = g_A + (size_t)r * WS + r + h * FC_IN;

    float acc[FC_OUT];
    #pragma unroll
    for (int o = 0; o < FC_OUT; o++) acc[o] = 0.0f;

    #pragma unroll 4
    for (int k = lane; k < FC_IN; k += 32) {
        float xv = x[k];
        #pragma unroll
        for (int o = 0; o < FC_OUT; o++)
            acc[o] = fmaf(xv, sw[o][k], acc[o]);
    }
    #pragma unroll
    for (int o = 0; o < FC_OUT; o++) {
        #pragma unroll
        for (int d = 16; d > 0; d >>= 1)
            acc[o] += __shfl_down_sync(0xffffffffu, acc[o], d);
    }
    if (lane == 0) {
        #pragma unroll
        for (int o = 0; o < FC_OUT; o++)
            out[(size_t)m * FC_OUT + o] = acc[o] + fc_b[o];
    }
}

// ---------------- launch ----------------
extern "C" void kernel_launch(void* const* d_in, const int* in_sizes, int n_in,
                              void* d_out, int out_size)
{
    (void)in_sizes; (void)n_in; (void)out_size;
    const float* x       = (const float*)d_in[0];  // [1,2048,2048]
    const float* w_in    = (const float*)d_in[1];  // [1]
    const float* b_in    = (const float*)d_in[2];  // [1]
    const float* w_state = (const float*)d_in[3];  // [2] = {k0, k1}
    const float* b_state = (const float*)d_in[4];  // [1]
    const float* fc_w    = (const float*)d_in[5];  // [10,1024]
    const float* fc_b    = (const float*)d_in[6];  // [10]
    float* out = (float*)d_out;                    // [4096,10]

    prep_kernel<<<(HH * (WS / 4)) / 256, 256>>>(x, w_in, b_in, w_state, b_state);
    scan_kernel<<<NSTAGE, 32>>>(w_state);
    fc_kernel<<<M_ROWS / 8, 256>>>(fc_w, fc_b, out);
}